// round 10
// baseline (speedup 1.0000x reference)
#include <cuda_runtime.h>

#define NN 8192
#define TPB 256
#define NWARP (TPB / 32)
#define KW (NN / 4 / 32)      // 64 float4 per lane per row
#define EPS 1e-5f
#define GRID_MV 592           // 148 SMs x 4 CTAs

// ---------------- device scratch ----------------
__device__ float g_stats[12];   // 6 BN stages x (sum, sumsq)
__device__ int   g_q[8];        // row-ticket queues: 0,1=mv1  2,3=mv2  4=mv3  5=mv4
__device__ __align__(16) float g_y1[NN], g_y2[NN];
__device__ __align__(16) float g_gg1[NN], g_gg2[NN];
__device__ __align__(16) float g_z1[NN], g_z2[NN];
__device__ __align__(16) float g_f0[NN], g_f1[NN];
__device__ __align__(16) float g_u0[NN], g_u1[NN];
__device__ __align__(16) float g_g3[NN], g_z3[NN];

__global__ void zero_kernel() {
    if (threadIdx.x < 12) g_stats[threadIdx.x] = 0.f;
    if (threadIdx.x < 8)  g_q[threadIdx.x] = 0;
}

__device__ __forceinline__ float2 bn_coeffs(int slot, float cnt, float ga, float be) {
    float m = g_stats[2 * slot] / cnt;
    float v = g_stats[2 * slot + 1] / cnt - m * m;
    float scale = ga * rsqrtf(v + EPS);
    return make_float2(scale, be - m * scale);   // f = h*scale + shift
}

// block stats flush
__device__ __forceinline__ void flush_stats(float s, float s2, float (*sred)[2],
                                            int lane, int wid, int tid, float* dst) {
    if (lane == 0) { sred[wid][0] = s; sred[wid][1] = s2; }
    __syncthreads();
    if (tid == 0) {
        float a = 0.f, b = 0.f;
#pragma unroll
        for (int i = 0; i < NWARP; i++) { a += sred[i][0]; b += sred[i][1]; }
        atomicAdd(dst, a);
        atomicAdd(dst + 1, b);
    }
}

// warp row dot: A bypasses L1 (.cg / .cs), x via L1 (__ldg). Result on all lanes.
template <bool STREAM>
__device__ __forceinline__ float warp_row_dot(const float* __restrict__ A, int row,
                                              const float4* __restrict__ x4, int lane) {
    const float4* a4 = (const float4*)(A + (size_t)row * NN);
    float acc0 = 0.f, acc1 = 0.f, acc2 = 0.f, acc3 = 0.f;
#pragma unroll
    for (int k = 0; k < KW; k += 4) {
        float4 a0 = STREAM ? __ldcs(a4 + lane + (k + 0) * 32) : __ldcg(a4 + lane + (k + 0) * 32);
        float4 a1 = STREAM ? __ldcs(a4 + lane + (k + 1) * 32) : __ldcg(a4 + lane + (k + 1) * 32);
        float4 a2 = STREAM ? __ldcs(a4 + lane + (k + 2) * 32) : __ldcg(a4 + lane + (k + 2) * 32);
        float4 a3 = STREAM ? __ldcs(a4 + lane + (k + 3) * 32) : __ldcg(a4 + lane + (k + 3) * 32);
        float4 x0 = __ldg(x4 + lane + (k + 0) * 32);
        float4 x1 = __ldg(x4 + lane + (k + 1) * 32);
        float4 x2 = __ldg(x4 + lane + (k + 2) * 32);
        float4 x3 = __ldg(x4 + lane + (k + 3) * 32);
        acc0 = fmaf(a0.x, x0.x, acc0); acc0 = fmaf(a0.y, x0.y, acc0);
        acc0 = fmaf(a0.z, x0.z, acc0); acc0 = fmaf(a0.w, x0.w, acc0);
        acc1 = fmaf(a1.x, x1.x, acc1); acc1 = fmaf(a1.y, x1.y, acc1);
        acc1 = fmaf(a1.z, x1.z, acc1); acc1 = fmaf(a1.w, x1.w, acc1);
        acc2 = fmaf(a2.x, x2.x, acc2); acc2 = fmaf(a2.y, x2.y, acc2);
        acc2 = fmaf(a2.z, x2.z, acc2); acc2 = fmaf(a2.w, x2.w, acc2);
        acc3 = fmaf(a3.x, x3.x, acc3); acc3 = fmaf(a3.y, x3.y, acc3);
        acc3 = fmaf(a3.z, x3.z, acc3); acc3 = fmaf(a3.w, x3.w, acc3);
    }
    float acc = (acc0 + acc1) + (acc2 + acc3);
#pragma unroll
    for (int o = 16; o > 0; o >>= 1) acc += __shfl_xor_sync(0xffffffffu, acc, o);
    return acc;
}

// ---- pass 1 (dual, queue-scheduled): y = A @ F ; stats over relu(y*w+b) -> slot mat
__global__ __launch_bounds__(TPB) void mv1(
    const float* __restrict__ A1, const float* __restrict__ A2,
    const float* __restrict__ x,
    const float* __restrict__ w11, const float* __restrict__ b11,
    const float* __restrict__ w21, const float* __restrict__ b21)
{
    __shared__ float sred[NWARP][2];
    int tid = threadIdx.x, lane = tid & 31, wid = tid >> 5;
    int mat = blockIdx.x & 1;
    const float* A  = mat ? A2 : A1;
    const float4* x4 = (const float4*)(x + mat * NN);
    float*       yp = mat ? g_y2 : g_y1;
    const float* w  = mat ? w21 : w11;
    const float* b  = mat ? b21 : b11;
    float w0 = w[0], w1 = w[1], w2 = w[2], w3 = w[3];
    float b0 = b[0], b1 = b[1], b2 = b[2], b3 = b[3];

    float s = 0.f, s2 = 0.f;
    int cur = 0;
    if (lane == 0) cur = atomicAdd(&g_q[mat], 1);
    cur = __shfl_sync(0xffffffffu, cur, 0);
    while (cur < NN) {
        int nxt = 0;
        if (lane == 0) nxt = atomicAdd(&g_q[mat], 1);   // prefetch: latency hides under dot
        float t = warp_row_dot<false>(A, cur, x4, lane);
        nxt = __shfl_sync(0xffffffffu, nxt, 0);
        if (lane == 0) {
            yp[cur] = t;
            float v0 = fmaxf(fmaf(t, w0, b0), 0.f), v1 = fmaxf(fmaf(t, w1, b1), 0.f);
            float v2 = fmaxf(fmaf(t, w2, b2), 0.f), v3 = fmaxf(fmaf(t, w3, b3), 0.f);
            s  += v0 + v1 + v2 + v3;
            s2 += v0 * v0 + v1 * v1 + v2 * v2 + v3 * v3;
        }
        cur = nxt;
    }
    flush_stats(s, s2, sred, lane, wid, tid, &g_stats[2 * mat]);
}

// ---- transform: g1,g2 from y1,y2 (BN slots 0,1)
__global__ void t2_kernel(
    const float* __restrict__ w11, const float* __restrict__ b11, const float* __restrict__ w12,
    const float* __restrict__ w21, const float* __restrict__ b21, const float* __restrict__ w22,
    const float* __restrict__ gamma, const float* __restrict__ beta)
{
    float ga = gamma[0], be = beta[0];
    float2 c0 = bn_coeffs(0, (float)(NN * 4), ga, be);
    float2 c1 = bn_coeffs(1, (float)(NN * 4), ga, be);
    int j = blockIdx.x * blockDim.x + threadIdx.x;
    if (j >= NN) return;
    {
        float yy = g_y1[j];
        float h0 = fmaxf(fmaf(yy, w11[0], b11[0]), 0.f);
        float h1 = fmaxf(fmaf(yy, w11[1], b11[1]), 0.f);
        float h2 = fmaxf(fmaf(yy, w11[2], b11[2]), 0.f);
        float h3 = fmaxf(fmaf(yy, w11[3], b11[3]), 0.f);
        g_gg1[j] = w12[0] * fmaf(h0, c0.x, c0.y) + w12[1] * fmaf(h1, c0.x, c0.y)
                 + w12[2] * fmaf(h2, c0.x, c0.y) + w12[3] * fmaf(h3, c0.x, c0.y);
    }
    {
        float yy = g_y2[j];
        float h0 = fmaxf(fmaf(yy, w21[0], b21[0]), 0.f);
        float h1 = fmaxf(fmaf(yy, w21[1], b21[1]), 0.f);
        float h2 = fmaxf(fmaf(yy, w21[2], b21[2]), 0.f);
        float h3 = fmaxf(fmaf(yy, w21[3], b21[3]), 0.f);
        g_gg2[j] = w22[0] * fmaf(h0, c1.x, c1.y) + w22[1] * fmaf(h1, c1.x, c1.y)
                 + w22[2] * fmaf(h2, c1.x, c1.y) + w22[3] * fmaf(h3, c1.x, c1.y);
    }
}

// ---- pass 2 (dual, queue-scheduled): z = A @ g ; stats over relu(z+b) -> slot 2+mat
__global__ __launch_bounds__(TPB) void mv2(
    const float* __restrict__ A1, const float* __restrict__ A2,
    const float* __restrict__ b12, const float* __restrict__ b22)
{
    __shared__ float sred[NWARP][2];
    int tid = threadIdx.x, lane = tid & 31, wid = tid >> 5;
    int mat = blockIdx.x & 1;
    const float* A = mat ? A2 : A1;
    const float4* x4 = (const float4*)(mat ? g_gg2 : g_gg1);
    float* zp = mat ? g_z2 : g_z1;
    float bb = mat ? b22[0] : b12[0];

    float s = 0.f, s2 = 0.f;
    int cur = 0;
    if (lane == 0) cur = atomicAdd(&g_q[2 + mat], 1);
    cur = __shfl_sync(0xffffffffu, cur, 0);
    while (cur < NN) {
        int nxt = 0;
        if (lane == 0) nxt = atomicAdd(&g_q[2 + mat], 1);
        float t = warp_row_dot<true>(A, cur, x4, lane);
        nxt = __shfl_sync(0xffffffffu, nxt, 0);
        if (lane == 0) {
            zp[cur] = t;
            float v = fmaxf(t + bb, 0.f);
            s += v; s2 += v * v;
        }
        cur = nxt;
    }
    flush_stats(s, s2, sred, lane, wid, tid, &g_stats[2 * (2 + mat)]);
}

// ---- transform: f0,f1 from z1,z2 (BN slots 2,3)
__global__ void t3_kernel(
    const float* __restrict__ b12, const float* __restrict__ b22,
    const float* __restrict__ gamma, const float* __restrict__ beta)
{
    float ga = gamma[0], be = beta[0];
    float2 c2 = bn_coeffs(2, (float)NN, ga, be);
    float2 c3 = bn_coeffs(3, (float)NN, ga, be);
    float bb1 = b12[0], bb2 = b22[0];
    int j = blockIdx.x * blockDim.x + threadIdx.x;
    if (j >= NN) return;
    g_f0[j] = fmaxf(fmaf(fmaxf(g_z1[j] + bb1, 0.f), c2.x, c2.y), 0.f);
    g_f1[j] = fmaxf(fmaf(fmaxf(g_z2[j] + bb2, 0.f), c3.x, c3.y), 0.f);
}

// ---- pass 3 (queue-scheduled): (u0,u1) = A12 @ [f0 f1] ; stats -> slot 4
__global__ __launch_bounds__(TPB) void mv3(
    const float* __restrict__ A,
    const float* __restrict__ wc1, const float* __restrict__ bc1)
{
    __shared__ float sred[NWARP][2];
    int tid = threadIdx.x, lane = tid & 31, wid = tid >> 5;
    const float4* f04 = (const float4*)g_f0;
    const float4* f14 = (const float4*)g_f1;
    float wA0 = wc1[0], wA1 = wc1[1], wA2 = wc1[2], wA3 = wc1[3];
    float wB0 = wc1[4], wB1 = wc1[5], wB2 = wc1[6], wB3 = wc1[7];
    float bq0 = bc1[0], bq1 = bc1[1], bq2 = bc1[2], bq3 = bc1[3];

    float s = 0.f, s2 = 0.f;
    int cur = 0;
    if (lane == 0) cur = atomicAdd(&g_q[4], 1);
    cur = __shfl_sync(0xffffffffu, cur, 0);
    while (cur < NN) {
        int nxt = 0;
        if (lane == 0) nxt = atomicAdd(&g_q[4], 1);
        const float4* a4 = (const float4*)(A + (size_t)cur * NN);
        float p00 = 0.f, p01 = 0.f, p10 = 0.f, p11 = 0.f;
#pragma unroll
        for (int k = 0; k < KW; k += 2) {
            float4 a0 = __ldcg(a4 + lane + (k + 0) * 32);
            float4 a1 = __ldcg(a4 + lane + (k + 1) * 32);
            float4 u0 = __ldg(f04 + lane + (k + 0) * 32);
            float4 u1 = __ldg(f04 + lane + (k + 1) * 32);
            float4 v0 = __ldg(f14 + lane + (k + 0) * 32);
            float4 v1 = __ldg(f14 + lane + (k + 1) * 32);
            p00 = fmaf(a0.x, u0.x, p00); p00 = fmaf(a0.y, u0.y, p00);
            p00 = fmaf(a0.z, u0.z, p00); p00 = fmaf(a0.w, u0.w, p00);
            p01 = fmaf(a1.x, u1.x, p01); p01 = fmaf(a1.y, u1.y, p01);
            p01 = fmaf(a1.z, u1.z, p01); p01 = fmaf(a1.w, u1.w, p01);
            p10 = fmaf(a0.x, v0.x, p10); p10 = fmaf(a0.y, v0.y, p10);
            p10 = fmaf(a0.z, v0.z, p10); p10 = fmaf(a0.w, v0.w, p10);
            p11 = fmaf(a1.x, v1.x, p11); p11 = fmaf(a1.y, v1.y, p11);
            p11 = fmaf(a1.z, v1.z, p11); p11 = fmaf(a1.w, v1.w, p11);
        }
        float t0 = p00 + p01, t1 = p10 + p11;
#pragma unroll
        for (int o = 16; o > 0; o >>= 1) {
            t0 += __shfl_xor_sync(0xffffffffu, t0, o);
            t1 += __shfl_xor_sync(0xffffffffu, t1, o);
        }
        nxt = __shfl_sync(0xffffffffu, nxt, 0);
        if (lane == 0) {
            g_u0[cur] = t0;
            g_u1[cur] = t1;
            float v0 = fmaxf(t0 * wA0 + t1 * wB0 + bq0, 0.f);
            float v1 = fmaxf(t0 * wA1 + t1 * wB1 + bq1, 0.f);
            float v2 = fmaxf(t0 * wA2 + t1 * wB2 + bq2, 0.f);
            float v3 = fmaxf(t0 * wA3 + t1 * wB3 + bq3, 0.f);
            s  += v0 + v1 + v2 + v3;
            s2 += v0 * v0 + v1 * v1 + v2 * v2 + v3 * v3;
        }
        cur = nxt;
    }
    flush_stats(s, s2, sred, lane, wid, tid, &g_stats[8]);
}

// ---- transform: g3 from u0,u1 (BN slot 4)
__global__ void t4_kernel(
    const float* __restrict__ wc1, const float* __restrict__ bc1,
    const float* __restrict__ wc2,
    const float* __restrict__ gamma, const float* __restrict__ beta)
{
    float2 c = bn_coeffs(4, (float)(NN * 4), gamma[0], beta[0]);
    int j = blockIdx.x * blockDim.x + threadIdx.x;
    if (j >= NN) return;
    float t0 = g_u0[j], t1 = g_u1[j];
    float h0 = fmaxf(t0 * wc1[0] + t1 * wc1[4] + bc1[0], 0.f);
    float h1 = fmaxf(t0 * wc1[1] + t1 * wc1[5] + bc1[1], 0.f);
    float h2 = fmaxf(t0 * wc1[2] + t1 * wc1[6] + bc1[2], 0.f);
    float h3 = fmaxf(t0 * wc1[3] + t1 * wc1[7] + bc1[3], 0.f);
    g_g3[j] = wc2[0] * fmaf(h0, c.x, c.y) + wc2[1] * fmaf(h1, c.x, c.y)
            + wc2[2] * fmaf(h2, c.x, c.y) + wc2[3] * fmaf(h3, c.x, c.y);
}

// ---- pass 4 (queue-scheduled): z3 = A12 @ g3 ; stats relu(z3+bc2) -> slot 5
__global__ __launch_bounds__(TPB) void mv4(
    const float* __restrict__ A, const float* __restrict__ bc2)
{
    __shared__ float sred[NWARP][2];
    float bb = bc2[0];
    int tid = threadIdx.x, lane = tid & 31, wid = tid >> 5;
    const float4* x4 = (const float4*)g_g3;

    float s = 0.f, s2 = 0.f;
    int cur = 0;
    if (lane == 0) cur = atomicAdd(&g_q[5], 1);
    cur = __shfl_sync(0xffffffffu, cur, 0);
    while (cur < NN) {
        int nxt = 0;
        if (lane == 0) nxt = atomicAdd(&g_q[5], 1);
        float t = warp_row_dot<true>(A, cur, x4, lane);
        nxt = __shfl_sync(0xffffffffu, nxt, 0);
        if (lane == 0) {
            g_z3[cur] = t;
            float v = fmaxf(t + bb, 0.f);
            s += v; s2 += v * v;
        }
        cur = nxt;
    }
    flush_stats(s, s2, sred, lane, wid, tid, &g_stats[10]);
}

// ---- final: out = relu(BN(relu(z3 + bc2))) with slot 5
__global__ void final_kernel(const float* __restrict__ bc2,
                             const float* __restrict__ gamma, const float* __restrict__ beta,
                             float* __restrict__ out)
{
    float2 c = bn_coeffs(5, (float)NN, gamma[0], beta[0]);
    float bb = bc2[0];
    int j = blockIdx.x * blockDim.x + threadIdx.x;
    if (j >= NN) return;
    float h = fmaxf(g_z3[j] + bb, 0.f);
    out[j] = fmaxf(fmaf(h, c.x, c.y), 0.f);
}

// ---------------- launch ----------------
extern "C" void kernel_launch(void* const* d_in, const int* in_sizes, int n_in,
                              void* d_out, int out_size)
{
    const float* x     = (const float*)d_in[0];
    const float* adj   = (const float*)d_in[1];
    const float* w11   = (const float*)d_in[2];
    const float* b11   = (const float*)d_in[3];
    const float* w12   = (const float*)d_in[4];
    const float* b12   = (const float*)d_in[5];
    const float* w21   = (const float*)d_in[6];
    const float* b21   = (const float*)d_in[7];
    const float* w22   = (const float*)d_in[8];
    const float* b22   = (const float*)d_in[9];
    const float* wc1   = (const float*)d_in[10];
    const float* bc1   = (const float*)d_in[11];
    const float* wc2   = (const float*)d_in[12];
    const float* bc2   = (const float*)d_in[13];
    const float* gamma = (const float*)d_in[14];
    const float* beta  = (const float*)d_in[15];
    float* out = (float*)d_out;

    const float* A1  = adj;
    const float* A2  = adj + (size_t)NN * NN;
    const float* A12 = adj + 2 * (size_t)NN * NN;

    const int TB = 256, GB = NN / 256;

    zero_kernel<<<1, 32>>>();
    mv1<<<GRID_MV, TPB>>>(A1, A2, x, w11, b11, w21, b21);
    t2_kernel<<<GB, TB>>>(w11, b11, w12, w21, b21, w22, gamma, beta);
    mv2<<<GRID_MV, TPB>>>(A1, A2, b12, b22);
    t3_kernel<<<GB, TB>>>(b12, b22, gamma, beta);
    mv3<<<GRID_MV, TPB>>>(A12, wc1, bc1);
    t4_kernel<<<GB, TB>>>(wc1, bc1, wc2, gamma, beta);
    mv4<<<GRID_MV, TPB>>>(A12, bc2);
    final_kernel<<<GB, TB>>>(bc2, gamma, beta, out);

    (void)in_sizes; (void)n_in; (void)out_size;
}

// round 11
// speedup vs baseline: 1.1981x; 1.1981x over previous
#include <cuda_runtime.h>

#define NN 8192
#define TPB 256
#define NWARP (TPB / 32)
#define K4 (NN / 4 / TPB)     // 8 float4 per thread for full-vector staging
#define KW (NN / 4 / 32)      // 64 float4 per lane per full row
#define EPS 1e-5f

// ---------------- device scratch ----------------
__device__ float g_stats[12];   // 6 BN stages x (sum, sumsq)
__device__ __align__(16) float g_y1[NN], g_y2[NN];
__device__ __align__(16) float g_z1[NN], g_z2[NN];
__device__ __align__(16) float g_u0[NN], g_u1[NN];
__device__ __align__(16) float g_z3[NN];

__global__ void zero_kernel() {
    int j = blockIdx.x * blockDim.x + threadIdx.x;
    if (j < NN) { g_u0[j] = 0.f; g_u1[j] = 0.f; }
    if (j < 12) g_stats[j] = 0.f;
}

__device__ __forceinline__ float2 bn_coeffs(int slot, float cnt, float ga, float be) {
    float m = g_stats[2 * slot] / cnt;
    float v = g_stats[2 * slot + 1] / cnt - m * m;
    float scale = ga * rsqrtf(v + EPS);
    return make_float2(scale, be - m * scale);   // f = h*scale + shift
}

// warp-cooperative row dot over full row: one warp owns the row. 4 acc chains.
template <bool STREAM>
__device__ __forceinline__ float warp_row_dot(const float* __restrict__ A, int row,
                                              const float4* xs, int lane) {
    const float4* a4 = (const float4*)(A + (size_t)row * NN);
    float acc0 = 0.f, acc1 = 0.f, acc2 = 0.f, acc3 = 0.f;
#pragma unroll
    for (int k = 0; k < KW; k += 4) {
        float4 a0 = STREAM ? __ldcs(a4 + lane + (k + 0) * 32) : __ldg(a4 + lane + (k + 0) * 32);
        float4 a1 = STREAM ? __ldcs(a4 + lane + (k + 1) * 32) : __ldg(a4 + lane + (k + 1) * 32);
        float4 a2 = STREAM ? __ldcs(a4 + lane + (k + 2) * 32) : __ldg(a4 + lane + (k + 2) * 32);
        float4 a3 = STREAM ? __ldcs(a4 + lane + (k + 3) * 32) : __ldg(a4 + lane + (k + 3) * 32);
        float4 x0 = xs[lane + (k + 0) * 32];
        float4 x1 = xs[lane + (k + 1) * 32];
        float4 x2 = xs[lane + (k + 2) * 32];
        float4 x3 = xs[lane + (k + 3) * 32];
        acc0 = fmaf(a0.x, x0.x, acc0); acc0 = fmaf(a0.y, x0.y, acc0);
        acc0 = fmaf(a0.z, x0.z, acc0); acc0 = fmaf(a0.w, x0.w, acc0);
        acc1 = fmaf(a1.x, x1.x, acc1); acc1 = fmaf(a1.y, x1.y, acc1);
        acc1 = fmaf(a1.z, x1.z, acc1); acc1 = fmaf(a1.w, x1.w, acc1);
        acc2 = fmaf(a2.x, x2.x, acc2); acc2 = fmaf(a2.y, x2.y, acc2);
        acc2 = fmaf(a2.z, x2.z, acc2); acc2 = fmaf(a2.w, x2.w, acc2);
        acc3 = fmaf(a3.x, x3.x, acc3); acc3 = fmaf(a3.y, x3.y, acc3);
        acc3 = fmaf(a3.z, x3.z, acc3); acc3 = fmaf(a3.w, x3.w, acc3);
    }
    float acc = (acc0 + acc1) + (acc2 + acc3);
#pragma unroll
    for (int o = 16; o > 0; o >>= 1) acc += __shfl_xor_sync(0xffffffffu, acc, o);
    return acc;   // valid on all lanes
}

// block-level stats flush
__device__ __forceinline__ void flush_stats(float s, float s2, float (*sred)[2],
                                            int lane, int wid, int tid, float* dst) {
    if (lane == 0) { sred[wid][0] = s; sred[wid][1] = s2; }
    __syncthreads();
    if (tid == 0) {
        float a = 0.f, b = 0.f;
#pragma unroll
        for (int i = 0; i < NWARP; i++) { a += sred[i][0]; b += sred[i][1]; }
        atomicAdd(dst, a);
        atomicAdd(dst + 1, b);
    }
}

// ---- pass 1 (dual via z): y = A @ F ; stats over relu(y*w+b) [N,4] -> slot z
__global__ __launch_bounds__(TPB) void mv1(
    const float* __restrict__ Aa, const float* __restrict__ Ab,
    const float* __restrict__ x,
    const float* __restrict__ w11, const float* __restrict__ b11,
    const float* __restrict__ w21, const float* __restrict__ b21)
{
    __shared__ float4 xs[NN / 4];
    __shared__ float sred[NWARP][2];
    int z = blockIdx.z;
    const float* A  = z ? Ab : Aa;
    const float* xp = x + z * NN;
    float*       yp = z ? g_y2 : g_y1;
    const float* w  = z ? w21 : w11;
    const float* b  = z ? b21 : b11;
    int tid = threadIdx.x, lane = tid & 31, wid = tid >> 5;
    const float4* x4 = (const float4*)xp;
#pragma unroll
    for (int k = 0; k < K4; k++) xs[tid + k * TPB] = x4[tid + k * TPB];
    __syncthreads();

    int row = blockIdx.x * NWARP + wid;
    float t = warp_row_dot<false>(A, row, xs, lane);

    float s = 0.f, s2 = 0.f;
    if (lane == 0) {
        yp[row] = t;
        float v0 = fmaxf(fmaf(t, w[0], b[0]), 0.f), v1 = fmaxf(fmaf(t, w[1], b[1]), 0.f);
        float v2 = fmaxf(fmaf(t, w[2], b[2]), 0.f), v3 = fmaxf(fmaf(t, w[3], b[3]), 0.f);
        s  = v0 + v1 + v2 + v3;
        s2 = v0 * v0 + v1 * v1 + v2 * v2 + v3 * v3;
    }
    flush_stats(s, s2, sred, lane, wid, tid, &g_stats[2 * z]);
}

// ---- pass 2 (dual): prologue builds g from y (slot z); z = A @ g reversed;
//      stats over relu(z+b) -> slot 2+z
__global__ __launch_bounds__(TPB) void mv2(
    const float* __restrict__ Aa, const float* __restrict__ Ab,
    const float* __restrict__ w11, const float* __restrict__ b11, const float* __restrict__ w12,
    const float* __restrict__ w21, const float* __restrict__ b21, const float* __restrict__ w22,
    const float* __restrict__ b12, const float* __restrict__ b22,
    const float* __restrict__ gamma, const float* __restrict__ beta)
{
    __shared__ float4 xs[NN / 4];
    __shared__ float sred[NWARP][2];
    int z = blockIdx.z;
    const float* A   = z ? Ab : Aa;
    const float* y   = z ? g_y2 : g_y1;
    float*       zp  = z ? g_z2 : g_z1;
    const float* w1v = z ? w21 : w11;
    const float* b1v = z ? b21 : b11;
    const float* w2v = z ? w22 : w12;
    float bb = z ? b22[0] : b12[0];
    float2 c = bn_coeffs(z, (float)(NN * 4), gamma[0], beta[0]);
    float wa0 = w1v[0], wa1 = w1v[1], wa2 = w1v[2], wa3 = w1v[3];
    float ba0 = b1v[0], ba1 = b1v[1], ba2 = b1v[2], ba3 = b1v[3];
    float wb0 = w2v[0], wb1 = w2v[1], wb2 = w2v[2], wb3 = w2v[3];
    int tid = threadIdx.x, lane = tid & 31, wid = tid >> 5;
    const float4* y4 = (const float4*)y;
#pragma unroll
    for (int k = 0; k < K4; k++) {
        float4 yv = y4[tid + k * TPB];
        float4 gv;
        float* pi = (float*)&yv; float* po = (float*)&gv;
#pragma unroll
        for (int e = 0; e < 4; e++) {
            float yy = pi[e];
            float h0 = fmaxf(fmaf(yy, wa0, ba0), 0.f);
            float h1 = fmaxf(fmaf(yy, wa1, ba1), 0.f);
            float h2 = fmaxf(fmaf(yy, wa2, ba2), 0.f);
            float h3 = fmaxf(fmaf(yy, wa3, ba3), 0.f);
            po[e] = wb0 * fmaf(h0, c.x, c.y) + wb1 * fmaf(h1, c.x, c.y)
                  + wb2 * fmaf(h2, c.x, c.y) + wb3 * fmaf(h3, c.x, c.y);
        }
        xs[tid + k * TPB] = gv;
    }
    __syncthreads();

    int row = NN - 1 - (blockIdx.x * NWARP + wid);
    float t = warp_row_dot<true>(A, row, xs, lane);

    float s = 0.f, s2 = 0.f;
    if (lane == 0) {
        zp[row] = t;
        float v = fmaxf(t + bb, 0.f);
        s = v; s2 = v * v;
    }
    flush_stats(s, s2, sred, lane, wid, tid, &g_stats[2 * (2 + z)]);
}

// ---- pass 3 (dual via z = K-half, SPLIT-K): each CTA stages 32KB half of (f0,f1);
//      partial (u0,u1) accumulated via atomicAdd (2 addends -> deterministic).
__global__ __launch_bounds__(TPB) void mv3(
    const float* __restrict__ A,
    const float* __restrict__ b12, const float* __restrict__ b22,
    const float* __restrict__ gamma, const float* __restrict__ beta)
{
    __shared__ float4 xs0[NN / 8];   // 16 KB: f0 half
    __shared__ float4 xs1[NN / 8];   // 16 KB: f1 half
    int tid = threadIdx.x, lane = tid & 31, wid = tid >> 5;
    int half = blockIdx.z;
    int base4 = half * (NN / 8);     // float4 offset of this half
    float ga = gamma[0], be = beta[0];
    float2 c2 = bn_coeffs(2, (float)NN, ga, be);
    float2 c3 = bn_coeffs(3, (float)NN, ga, be);
    float bb1 = b12[0], bb2 = b22[0];
    const float4* z14 = (const float4*)g_z1 + base4;
    const float4* z24 = (const float4*)g_z2 + base4;
#pragma unroll
    for (int k = 0; k < (NN / 8) / TPB; k++) {     // 4 float4 per thread per array
        float4 a = __ldg(z14 + tid + k * TPB);
        float4 b = __ldg(z24 + tid + k * TPB);
        float* pa = (float*)&a; float* pb = (float*)&b;
#pragma unroll
        for (int e = 0; e < 4; e++) {
            pa[e] = fmaxf(fmaf(fmaxf(pa[e] + bb1, 0.f), c2.x, c2.y), 0.f);
            pb[e] = fmaxf(fmaf(fmaxf(pb[e] + bb2, 0.f), c3.x, c3.y), 0.f);
        }
        xs0[tid + k * TPB] = a;
        xs1[tid + k * TPB] = b;
    }
    __syncthreads();

    int row = blockIdx.x * NWARP + wid;
    const float4* a4 = (const float4*)(A + (size_t)row * NN) + base4;
    float p00 = 0.f, p01 = 0.f, p10 = 0.f, p11 = 0.f;
#pragma unroll
    for (int k = 0; k < KW / 2; k += 2) {          // 32 float4 per lane (half row)
        float4 a0 = __ldg(a4 + lane + (k + 0) * 32);
        float4 a1 = __ldg(a4 + lane + (k + 1) * 32);
        float4 u0 = xs0[lane + (k + 0) * 32];
        float4 u1 = xs0[lane + (k + 1) * 32];
        float4 v0 = xs1[lane + (k + 0) * 32];
        float4 v1 = xs1[lane + (k + 1) * 32];
        p00 = fmaf(a0.x, u0.x, p00); p00 = fmaf(a0.y, u0.y, p00);
        p00 = fmaf(a0.z, u0.z, p00); p00 = fmaf(a0.w, u0.w, p00);
        p01 = fmaf(a1.x, u1.x, p01); p01 = fmaf(a1.y, u1.y, p01);
        p01 = fmaf(a1.z, u1.z, p01); p01 = fmaf(a1.w, u1.w, p01);
        p10 = fmaf(a0.x, v0.x, p10); p10 = fmaf(a0.y, v0.y, p10);
        p10 = fmaf(a0.z, v0.z, p10); p10 = fmaf(a0.w, v0.w, p10);
        p11 = fmaf(a1.x, v1.x, p11); p11 = fmaf(a1.y, v1.y, p11);
        p11 = fmaf(a1.z, v1.z, p11); p11 = fmaf(a1.w, v1.w, p11);
    }
    float t0 = p00 + p01, t1 = p10 + p11;
#pragma unroll
    for (int o = 16; o > 0; o >>= 1) {
        t0 += __shfl_xor_sync(0xffffffffu, t0, o);
        t1 += __shfl_xor_sync(0xffffffffu, t1, o);
    }
    if (lane == 0) {
        atomicAdd(&g_u0[row], t0);
        atomicAdd(&g_u1[row], t1);
    }
}

// ---- stats for concat-block-1 activations (slot 4), from completed u0,u1
__global__ void stats4_kernel(const float* __restrict__ wc1, const float* __restrict__ bc1)
{
    __shared__ float sred[NWARP][2];
    int tid = threadIdx.x, lane = tid & 31, wid = tid >> 5;
    float wA0 = wc1[0], wA1 = wc1[1], wA2 = wc1[2], wA3 = wc1[3];
    float wB0 = wc1[4], wB1 = wc1[5], wB2 = wc1[6], wB3 = wc1[7];
    float bq0 = bc1[0], bq1 = bc1[1], bq2 = bc1[2], bq3 = bc1[3];
    float s = 0.f, s2 = 0.f;
    for (int j = blockIdx.x * blockDim.x + tid; j < NN; j += gridDim.x * blockDim.x) {
        float t0 = g_u0[j], t1 = g_u1[j];
        float v0 = fmaxf(t0 * wA0 + t1 * wB0 + bq0, 0.f);
        float v1 = fmaxf(t0 * wA1 + t1 * wB1 + bq1, 0.f);
        float v2 = fmaxf(t0 * wA2 + t1 * wB2 + bq2, 0.f);
        float v3 = fmaxf(t0 * wA3 + t1 * wB3 + bq3, 0.f);
        s  += v0 + v1 + v2 + v3;
        s2 += v0 * v0 + v1 * v1 + v2 * v2 + v3 * v3;
    }
    // warp reduce then block flush
#pragma unroll
    for (int o = 16; o > 0; o >>= 1) {
        s  += __shfl_xor_sync(0xffffffffu, s,  o);
        s2 += __shfl_xor_sync(0xffffffffu, s2, o);
    }
    flush_stats(s, s2, sred, lane, wid, tid, &g_stats[8]);
}

// ---- pass 4: prologue builds g3 from (u0,u1) (slot 4); z3 = A12 @ g3 reversed;
//      stats relu(z3+bc2) -> slot 5
__global__ __launch_bounds__(TPB) void mv4(
    const float* __restrict__ A,
    const float* __restrict__ wc1, const float* __restrict__ bc1,
    const float* __restrict__ wc2, const float* __restrict__ bc2,
    const float* __restrict__ gamma, const float* __restrict__ beta)
{
    __shared__ float4 xs[NN / 4];
    __shared__ float sred[NWARP][2];
    float2 c = bn_coeffs(4, (float)(NN * 4), gamma[0], beta[0]);
    float wA0 = wc1[0], wA1 = wc1[1], wA2 = wc1[2], wA3 = wc1[3];
    float wB0 = wc1[4], wB1 = wc1[5], wB2 = wc1[6], wB3 = wc1[7];
    float bq0 = bc1[0], bq1 = bc1[1], bq2 = bc1[2], bq3 = bc1[3];
    float wo0 = wc2[0], wo1 = wc2[1], wo2 = wc2[2], wo3 = wc2[3];
    float bb = bc2[0];
    int tid = threadIdx.x, lane = tid & 31, wid = tid >> 5;
    const float4* u04 = (const float4*)g_u0;
    const float4* u14 = (const float4*)g_u1;
#pragma unroll
    for (int k = 0; k < K4; k++) {
        float4 a = u04[tid + k * TPB];
        float4 b = u14[tid + k * TPB];
        float4 gv;
        float* pa = (float*)&a; float* pb = (float*)&b; float* po = (float*)&gv;
#pragma unroll
        for (int e = 0; e < 4; e++) {
            float t0 = pa[e], t1 = pb[e];
            float h0 = fmaxf(t0 * wA0 + t1 * wB0 + bq0, 0.f);
            float h1 = fmaxf(t0 * wA1 + t1 * wB1 + bq1, 0.f);
            float h2 = fmaxf(t0 * wA2 + t1 * wB2 + bq2, 0.f);
            float h3 = fmaxf(t0 * wA3 + t1 * wB3 + bq3, 0.f);
            po[e] = wo0 * fmaf(h0, c.x, c.y) + wo1 * fmaf(h1, c.x, c.y)
                  + wo2 * fmaf(h2, c.x, c.y) + wo3 * fmaf(h3, c.x, c.y);
        }
        xs[tid + k * TPB] = gv;
    }
    __syncthreads();

    int row = NN - 1 - (blockIdx.x * NWARP + wid);
    float t = warp_row_dot<true>(A, row, xs, lane);

    float s = 0.f, s2 = 0.f;
    if (lane == 0) {
        g_z3[row] = t;
        float v = fmaxf(t + bb, 0.f);
        s = v; s2 = v * v;
    }
    flush_stats(s, s2, sred, lane, wid, tid, &g_stats[10]);
}

// ---- final: out = relu(BN(relu(z3 + bc2))) with slot 5
__global__ void final_kernel(const float* __restrict__ bc2,
                             const float* __restrict__ gamma, const float* __restrict__ beta,
                             float* __restrict__ out)
{
    float2 c = bn_coeffs(5, (float)NN, gamma[0], beta[0]);
    float bb = bc2[0];
    int j = blockIdx.x * blockDim.x + threadIdx.x;
    if (j >= NN) return;
    float h = fmaxf(g_z3[j] + bb, 0.f);
    out[j] = fmaxf(fmaf(h, c.x, c.y), 0.f);
}

// ---------------- launch ----------------
extern "C" void kernel_launch(void* const* d_in, const int* in_sizes, int n_in,
                              void* d_out, int out_size)
{
    const float* x     = (const float*)d_in[0];
    const float* adj   = (const float*)d_in[1];
    const float* w11   = (const float*)d_in[2];
    const float* b11   = (const float*)d_in[3];
    const float* w12   = (const float*)d_in[4];
    const float* b12   = (const float*)d_in[5];
    const float* w21   = (const float*)d_in[6];
    const float* b21   = (const float*)d_in[7];
    const float* w22   = (const float*)d_in[8];
    const float* b22   = (const float*)d_in[9];
    const float* wc1   = (const float*)d_in[10];
    const float* bc1   = (const float*)d_in[11];
    const float* wc2   = (const float*)d_in[12];
    const float* bc2   = (const float*)d_in[13];
    const float* gamma = (const float*)d_in[14];
    const float* beta  = (const float*)d_in[15];
    float* out = (float*)d_out;

    const float* A1  = adj;
    const float* A2  = adj + (size_t)NN * NN;
    const float* A12 = adj + 2 * (size_t)NN * NN;

    dim3 g2(NN / NWARP, 1, 2);   // dual matrices
    dim3 g3(NN / NWARP, 1, 2);   // dual K-halves
    dim3 g1(NN / NWARP, 1, 1);

    zero_kernel<<<NN / 256, 256>>>();
    mv1<<<g2, TPB>>>(A1, A2, x, w11, b11, w21, b21);
    mv2<<<g2, TPB>>>(A1, A2, w11, b11, w12, w21, b21, w22, b12, b22, gamma, beta);
    mv3<<<g3, TPB>>>(A12, b12, b22, gamma, beta);
    stats4_kernel<<<32, 256>>>(wc1, bc1);
    mv4<<<g1, TPB>>>(A12, wc1, bc1, wc2, bc2, gamma, beta);
    final_kernel<<<NN / 256, 256>>>(bc2, gamma, beta, out);

    (void)in_sizes; (void)n_in; (void)out_size;
}